// round 4
// baseline (speedup 1.0000x reference)
#include <cuda_runtime.h>
#include <cuda_bf16.h>

// Problem constants (fixed by the dataset)
#define S_   8192
#define PF_  8
#define B_   32
#define E_   500000
#define NV_  50000

// ---------------- static device scratch (no allocs allowed) ----------------
// MX padded PF_ on BOTH sides: valid data at time index t+PF_.
__device__ float4 g_MX[2][S_ + 2 * PF_][B_][32];  // x@K+b_in per dir: (z,r,h,pad)
__device__ float  g_CUR[B_ * S_ * 64];    // GRU layer output, concat(f,b)
__device__ float  g_X1[B_ * S_ * 64];     // consistency-adjusted input to layer 1
__device__ float  g_SUMS[NV_ * 64];
__device__ float  g_VE[NV_ * 64];
__device__ float  g_CNT[NV_];

__device__ __forceinline__ float sigmoidf_(float x) {
    return __fdividef(1.0f, 1.0f + __expf(-x));
}
__device__ __forceinline__ float tanhf_(float x) {
    // tanh(x) = 1 - 2/(e^{2x}+1); saturates correctly at +/-1 for large |x|
    return 1.0f - __fdividef(2.0f, __expf(2.0f * x) + 1.0f);
}

// ---- packed fp32x2 helpers (Blackwell FFMA2: PTX fma.rn.f32x2 only) ----
__device__ __forceinline__ unsigned long long pk2(float lo, float hi) {
    unsigned long long r;
    asm("mov.b64 %0, {%1, %2};" : "=l"(r) : "f"(lo), "f"(hi));
    return r;
}
__device__ __forceinline__ void fma2(unsigned long long& d,
                                     unsigned long long a, unsigned long long b) {
    asm("fma.rn.f32x2 %0, %1, %2, %0;" : "+l"(d) : "l"(a), "l"(b));
}
__device__ __forceinline__ float sum2(unsigned long long v) {
    float a, b;
    asm("mov.b64 {%0, %1}, %2;" : "=f"(a), "=f"(b) : "l"(v));
    return a + b;
}

// ---------------- zero kernels ----------------
__global__ void zero_sums_kernel() {
    int i = blockIdx.x * 256 + threadIdx.x;
    if (i < NV_ * 64) g_SUMS[i] = 0.0f;
}
__global__ void zero_cnt_kernel() {
    int i = blockIdx.x * 256 + threadIdx.x;
    if (i < NV_) g_CNT[i] = 0.0f;
}

// ---------------- per-variable occurrence counts ----------------
__global__ void cnt_kernel(const int* __restrict__ var) {
    int e = blockIdx.x * 256 + threadIdx.x;
    if (e < E_) atomicAdd(&g_CNT[var[e]], 1.0f);
}

// ---------------- input GEMM: MX[d][t+PF][b][j] = (x*mask)@K + b_in ----------------
// grid (4096, 2), block 256. Tile = 64 consecutive tokens of one batch row.
__global__ void gemm_kernel(int use_emb,
                            const float* __restrict__ emb,
                            const int*   __restrict__ gidx,
                            const int*   __restrict__ slen,
                            const float* __restrict__ gk,   // [2][64][96] (this layer)
                            const float* __restrict__ gb)   // [2][2][96]  (this layer)
{
    __shared__ float Xs[64][64];
    __shared__ float Ks[64 * 96];

    int d    = blockIdx.y;
    int tile = blockIdx.x;
    int b    = tile >> 7;            // 128 tiles per batch row (8192/64)
    int t0   = (tile & 127) << 6;
    int tid  = threadIdx.x;
    int len  = slen[b];

    for (int i = tid; i < 64 * 64; i += 256) {
        int tt = i >> 6, k = i & 63;
        int t = t0 + tt;
        float v = 0.0f;
        if (t < len) {
            if (use_emb) {
                int id = gidx[b * S_ + t];
                v = emb[id * 64 + k];
            } else {
                v = g_X1[(b * S_ + t) * 64 + k];
            }
        }
        Xs[tt][k] = v;
    }
    const float* Kd = gk + d * 64 * 96;
    for (int i = tid; i < 64 * 96; i += 256) Ks[i] = Kd[i];
    __syncthreads();

    int j = tid & 31, tg = tid >> 5;
    float a0[8], a1[8], a2[8];
#pragma unroll
    for (int i = 0; i < 8; i++) { a0[i] = 0.f; a1[i] = 0.f; a2[i] = 0.f; }

#pragma unroll 4
    for (int k = 0; k < 64; k++) {
        float kz = Ks[k * 96 + j];
        float kr = Ks[k * 96 + 32 + j];
        float kh = Ks[k * 96 + 64 + j];
#pragma unroll
        for (int i = 0; i < 8; i++) {
            float x = Xs[tg * 8 + i][k];
            a0[i] = fmaf(x, kz, a0[i]);
            a1[i] = fmaf(x, kr, a1[i]);
            a2[i] = fmaf(x, kh, a2[i]);
        }
    }

    const float* bin = gb + d * 192;          // b_in for this dir
    float bz = bin[j], br = bin[32 + j], bh = bin[64 + j];
#pragma unroll
    for (int i = 0; i < 8; i++) {
        int t = t0 + tg * 8 + i;
        g_MX[d][t + PF_][b][j] = make_float4(a0[i] + bz, a1[i] + br, a2[i] + bh, 0.0f);
    }
}

// ---------------- GRU recurrence ----------------
// grid (16, 2): one warp per PAIR of batch streams (same direction -> shared
// packed R in registers). Lane j owns h[j] of both streams. The two
// independent latency chains (sync+LDS+fma2 chain+activations) interleave,
// filling the ~75% idle issue slots observed at one stream/warp.
// h broadcast via double-buffered smem rows; dot products via fma.rn.f32x2.
// Backward direction (d=1) consumes MX in REVERSE time order (scan reverse=True).
__global__ __launch_bounds__(32) void gru_kernel(const float* __restrict__ grec, // [2][32][96]
                                                 const float* __restrict__ gb)   // [2][2][96]
{
    __shared__ __align__(16) float hs[2][2][32];   // [stream][parity][lane]

    int j  = threadIdx.x;
    int d  = blockIdx.y;
    int pr = blockIdx.x;
    int b0 = 2 * pr, b1 = 2 * pr + 1;

    const float* R = grec + d * 32 * 96;
    // Packed k-pair coefficients: Rz2[p] = (R[2p][j], R[2p+1][j]) etc. 96 regs total.
    unsigned long long Rz2[16], Rr2[16], Rh2[16];
#pragma unroll
    for (int p = 0; p < 16; p++) {
        Rz2[p] = pk2(R[(2 * p) * 96 + j],      R[(2 * p + 1) * 96 + j]);
        Rr2[p] = pk2(R[(2 * p) * 96 + 32 + j], R[(2 * p + 1) * 96 + 32 + j]);
        Rh2[p] = pk2(R[(2 * p) * 96 + 64 + j], R[(2 * p + 1) * 96 + 64 + j]);
    }
    const float* brc = gb + d * 192 + 96;     // b_rec
    float bz = brc[j], br = brc[32 + j], bh = brc[64 + j];

    const bool fwd = (d == 0);
    // base pointer at valid-data start (time 0 lives at array index PF_);
    // index: time*1024 + b*32 + j. Backward prefetch may reach time -PF_,
    // which lands in the left padding — in bounds, never consumed.
    const float4* mx = &g_MX[d][PF_][0][0];

    float4 buf0[PF_], buf1[PF_];
#pragma unroll
    for (int p = 0; p < PF_; p++) {
        int tt = fwd ? p : (S_ - 1 - p);
        buf0[p] = mx[tt * 1024 + b0 * 32 + j];
        buf1[p] = mx[tt * 1024 + b1 * 32 + j];
    }

    float h0 = 0.0f, h1 = 0.0f;

    for (int t0 = 0; t0 < S_; t0 += PF_) {
#pragma unroll
        for (int p = 0; p < PF_; p++) {
            int t  = t0 + p;                       // step counter
            int tt = fwd ? t : (S_ - 1 - t);       // time index consumed this step
            int par = t & 1;

            hs[0][par][j] = h0;                    // publish h to the warp
            hs[1][par][j] = h1;

            float4 m0 = buf0[p], m1 = buf1[p];
            int tp = fwd ? (t + PF_) : (S_ - 1 - t - PF_);
            buf0[p] = mx[tp * 1024 + b0 * 32 + j]; // prefetch PF_ steps ahead
            buf1[p] = mx[tp * 1024 + b1 * 32 + j];

            __syncwarp();

            // accumulators: z/r fold in m + b_rec; h-gate holds only (h@Rh + b_rec_h)
            unsigned long long az0 = pk2(m0.x + bz, 0.0f);
            unsigned long long ar0 = pk2(m0.y + br, 0.0f);
            unsigned long long ah0 = pk2(bh, 0.0f);
            unsigned long long az1 = pk2(m1.x + bz, 0.0f);
            unsigned long long ar1 = pk2(m1.y + br, 0.0f);
            unsigned long long ah1 = pk2(bh, 0.0f);

            const ulonglong2* hv0 = (const ulonglong2*)hs[0][par];
            const ulonglong2* hv1 = (const ulonglong2*)hs[1][par];
#pragma unroll
            for (int q = 0; q < 8; q++) {
                ulonglong2 v0 = hv0[q];            // (h[4q],h[4q+1]) , (h[4q+2],h[4q+3])
                ulonglong2 v1 = hv1[q];
                fma2(az0, v0.x, Rz2[2 * q]);
                fma2(ar0, v0.x, Rr2[2 * q]);
                fma2(ah0, v0.x, Rh2[2 * q]);
                fma2(az1, v1.x, Rz2[2 * q]);
                fma2(ar1, v1.x, Rr2[2 * q]);
                fma2(ah1, v1.x, Rh2[2 * q]);
                fma2(az0, v0.y, Rz2[2 * q + 1]);
                fma2(ar0, v0.y, Rr2[2 * q + 1]);
                fma2(ah0, v0.y, Rh2[2 * q + 1]);
                fma2(az1, v1.y, Rz2[2 * q + 1]);
                fma2(ar1, v1.y, Rr2[2 * q + 1]);
                fma2(ah1, v1.y, Rh2[2 * q + 1]);
            }

            float z0  = sigmoidf_(sum2(az0));
            float r0  = sigmoidf_(sum2(ar0));
            float hh0 = tanhf_(fmaf(r0, sum2(ah0), m0.z));
            h0 = fmaf(z0, h0 - hh0, hh0);

            float z1  = sigmoidf_(sum2(az1));
            float r1  = sigmoidf_(sum2(ar1));
            float hh1 = tanhf_(fmaf(r1, sum2(ah1), m1.z));
            h1 = fmaf(z1, h1 - hh1, hh1);

            g_CUR[(b0 * S_ + tt) * 64 + d * 32 + j] = h0;
            g_CUR[(b1 * S_ + tt) * 64 + d * 32 + j] = h1;
        }
    }
}

// ---------------- segment sum: SUMS[var[e]][f] += CUR[tok[e]][f] ----------------
__global__ void segsum_kernel(const int* __restrict__ tok, const int* __restrict__ var) {
    int g = blockIdx.x * 256 + threadIdx.x;
    if (g >= E_ * 64) return;
    int e = g >> 6, f = g & 63;
    int t = tok[e], v = var[e];
    atomicAdd(&g_SUMS[v * 64 + f], g_CUR[t * 64 + f]);
}

// ---------------- VE = SUMS / max(CNT,1) ----------------
__global__ void div_kernel(float* __restrict__ out, int to_out) {
    int i = blockIdx.x * 256 + threadIdx.x;
    if (i >= NV_ * 64) return;
    float c = g_CNT[i >> 6];
    float v = __fdividef(g_SUMS[i], fmaxf(c, 1.0f));
    if (to_out) out[i] = v;
    else        g_VE[i] = v;
}

// ---------------- X1 = CUR (copy), then scatter-add VE back ----------------
__global__ void copy_kernel() {
    int i = blockIdx.x * 256 + threadIdx.x;
    const float4* s = reinterpret_cast<const float4*>(g_CUR);
    float4* dst = reinterpret_cast<float4*>(g_X1);
    if (i < B_ * S_ * 16) dst[i] = s[i];
}

__global__ void scatter_kernel(const int* __restrict__ tok, const int* __restrict__ var) {
    int g = blockIdx.x * 256 + threadIdx.x;
    if (g >= E_ * 64) return;
    int e = g >> 6, f = g & 63;
    atomicAdd(&g_X1[tok[e] * 64 + f], g_VE[var[e] * 64 + f]);
}

// ---------------- classification = VE @ W (reads VE from d_out first half) --------
__global__ void linear_kernel(const float* __restrict__ ve, const float* __restrict__ W,
                              float* __restrict__ out) {
    __shared__ float Ws[64 * 64];
    for (int i = threadIdx.x; i < 64 * 64; i += 256) Ws[i] = W[i];
    __syncthreads();
    int g = blockIdx.x * 256 + threadIdx.x;
    if (g >= NV_ * 64) return;
    int v = g >> 6, c = g & 63;
    float acc = 0.0f;
#pragma unroll
    for (int f = 0; f < 64; f++)
        acc = fmaf(__ldg(&ve[v * 64 + f]), Ws[f * 64 + c], acc);
    out[g] = acc;
}

// ---------------- launcher ----------------
extern "C" void kernel_launch(void* const* d_in, const int* in_sizes, int n_in,
                              void* d_out, int out_size) {
    const float* emb  = (const float*)d_in[0];   // [10000,64]
    const float* gk   = (const float*)d_in[1];   // [2][2][64][96]
    const float* grec = (const float*)d_in[2];   // [2][2][32][96]
    const float* gb   = (const float*)d_in[3];   // [2][2][2][96]
    const float* W    = (const float*)d_in[4];   // [64,64]
    const int*   gidx = (const int*)d_in[5];     // [32,8192]
    const int*   slen = (const int*)d_in[6];     // [32]
    const int*   tok  = (const int*)d_in[7];     // [500000]
    const int*   var  = (const int*)d_in[8];     // [500000]
    float* out = (float*)d_out;                  // [NV*64] ve, then [NV*64] cls

    const int EG  = (E_ * 64) / 256;     // 125000
    const int VG  = (NV_ * 64) / 256;    // 12500
    const int CG  = (NV_ + 255) / 256;
    const int EB  = (E_ + 255) / 256;
    const int CPG = (B_ * S_ * 16) / 256;

    // counts (identical for every var_emb call)
    zero_cnt_kernel<<<CG, 256>>>();
    cnt_kernel<<<EB, 256>>>(var);

    // -------- layer 0 --------
    gemm_kernel<<<dim3(4096, 2), 256>>>(1, emb, gidx, slen, gk, gb);
    gru_kernel<<<dim3(16, 2), 32>>>(grec, gb);

    // consistency: variable means -> scatter back
    zero_sums_kernel<<<VG, 256>>>();
    segsum_kernel<<<EG, 256>>>(tok, var);
    div_kernel<<<VG, 256>>>(out, 0);         // -> g_VE
    copy_kernel<<<CPG, 256>>>();             // X1 = CUR
    scatter_kernel<<<EG, 256>>>(tok, var);   // X1 += scattered VE

    // -------- layer 1 --------
    gemm_kernel<<<dim3(4096, 2), 256>>>(0, emb, gidx, slen,
                                        gk + 2 * 64 * 96, gb + 384);
    gru_kernel<<<dim3(16, 2), 32>>>(grec + 2 * 32 * 96, gb + 384);

    // final variable embeddings + classification head
    zero_sums_kernel<<<VG, 256>>>();
    segsum_kernel<<<EG, 256>>>(tok, var);
    div_kernel<<<VG, 256>>>(out, 1);         // -> d_out[0 : NV*64]
    linear_kernel<<<VG, 256>>>(out, W, out + NV_ * 64);
}

// round 5
// speedup vs baseline: 1.0154x; 1.0154x over previous
#include <cuda_runtime.h>
#include <cuda_bf16.h>

// Problem constants (fixed by the dataset)
#define S_   8192
#define PF_  8      // MX array padding (both sides)
#define PG_  4      // GRU prefetch depth per stream (register-budget limited)
#define B_   32
#define E_   500000
#define NV_  50000

// ---------------- static device scratch (no allocs allowed) ----------------
// MX padded PF_ on BOTH sides: valid data at time index t+PF_.
__device__ float4 g_MX[2][S_ + 2 * PF_][B_][32];  // x@K+b_in per dir: (z,r,h,pad)
__device__ float  g_CUR[B_ * S_ * 64];    // GRU layer output, concat(f,b)
__device__ float  g_X1[B_ * S_ * 64];     // consistency-adjusted input to layer 1
__device__ float  g_SUMS[NV_ * 64];
__device__ float  g_VE[NV_ * 64];
__device__ float  g_CNT[NV_];

__device__ __forceinline__ float sigmoidf_(float x) {
    return __fdividef(1.0f, 1.0f + __expf(-x));
}
__device__ __forceinline__ float tanhf_(float x) {
    // tanh(x) = 1 - 2/(e^{2x}+1); saturates correctly at +/-1 for large |x|
    return 1.0f - __fdividef(2.0f, __expf(2.0f * x) + 1.0f);
}

// ---- packed fp32x2 helpers (Blackwell FFMA2: PTX fma.rn.f32x2 only) ----
__device__ __forceinline__ unsigned long long pk2(float lo, float hi) {
    unsigned long long r;
    asm("mov.b64 %0, {%1, %2};" : "=l"(r) : "f"(lo), "f"(hi));
    return r;
}
__device__ __forceinline__ void fma2(unsigned long long& d,
                                     unsigned long long a, unsigned long long b) {
    asm("fma.rn.f32x2 %0, %1, %2, %0;" : "+l"(d) : "l"(a), "l"(b));
}
__device__ __forceinline__ float sum2(unsigned long long v) {
    float a, b;
    asm("mov.b64 {%0, %1}, %2;" : "=f"(a), "=f"(b) : "l"(v));
    return a + b;
}
__device__ __forceinline__ float sum22(unsigned long long u, unsigned long long v) {
    float a, b, c, d;
    asm("mov.b64 {%0, %1}, %2;" : "=f"(a), "=f"(b) : "l"(u));
    asm("mov.b64 {%0, %1}, %2;" : "=f"(c), "=f"(d) : "l"(v));
    return (a + b) + (c + d);
}

// ---------------- zero kernels ----------------
__global__ void zero_sums_kernel() {
    int i = blockIdx.x * 256 + threadIdx.x;
    if (i < NV_ * 64) g_SUMS[i] = 0.0f;
}
__global__ void zero_cnt_kernel() {
    int i = blockIdx.x * 256 + threadIdx.x;
    if (i < NV_) g_CNT[i] = 0.0f;
}

// ---------------- per-variable occurrence counts ----------------
__global__ void cnt_kernel(const int* __restrict__ var) {
    int e = blockIdx.x * 256 + threadIdx.x;
    if (e < E_) atomicAdd(&g_CNT[var[e]], 1.0f);
}

// ---------------- input GEMM: MX[d][t+PF][b][j] = (x*mask)@K + b_in ----------------
// grid (4096, 2), block 256. Tile = 64 consecutive tokens of one batch row.
__global__ void gemm_kernel(int use_emb,
                            const float* __restrict__ emb,
                            const int*   __restrict__ gidx,
                            const int*   __restrict__ slen,
                            const float* __restrict__ gk,   // [2][64][96] (this layer)
                            const float* __restrict__ gb)   // [2][2][96]  (this layer)
{
    __shared__ float Xs[64][64];
    __shared__ float Ks[64 * 96];

    int d    = blockIdx.y;
    int tile = blockIdx.x;
    int b    = tile >> 7;            // 128 tiles per batch row (8192/64)
    int t0   = (tile & 127) << 6;
    int tid  = threadIdx.x;
    int len  = slen[b];

    for (int i = tid; i < 64 * 64; i += 256) {
        int tt = i >> 6, k = i & 63;
        int t = t0 + tt;
        float v = 0.0f;
        if (t < len) {
            if (use_emb) {
                int id = gidx[b * S_ + t];
                v = emb[id * 64 + k];
            } else {
                v = g_X1[(b * S_ + t) * 64 + k];
            }
        }
        Xs[tt][k] = v;
    }
    const float* Kd = gk + d * 64 * 96;
    for (int i = tid; i < 64 * 96; i += 256) Ks[i] = Kd[i];
    __syncthreads();

    int j = tid & 31, tg = tid >> 5;
    float a0[8], a1[8], a2[8];
#pragma unroll
    for (int i = 0; i < 8; i++) { a0[i] = 0.f; a1[i] = 0.f; a2[i] = 0.f; }

#pragma unroll 4
    for (int k = 0; k < 64; k++) {
        float kz = Ks[k * 96 + j];
        float kr = Ks[k * 96 + 32 + j];
        float kh = Ks[k * 96 + 64 + j];
#pragma unroll
        for (int i = 0; i < 8; i++) {
            float x = Xs[tg * 8 + i][k];
            a0[i] = fmaf(x, kz, a0[i]);
            a1[i] = fmaf(x, kr, a1[i]);
            a2[i] = fmaf(x, kh, a2[i]);
        }
    }

    const float* bin = gb + d * 192;          // b_in for this dir
    float bz = bin[j], br = bin[32 + j], bh = bin[64 + j];
#pragma unroll
    for (int i = 0; i < 8; i++) {
        int t = t0 + tg * 8 + i;
        g_MX[d][t + PF_][b][j] = make_float4(a0[i] + bz, a1[i] + br, a2[i] + bh, 0.0f);
    }
}

// ---------------- GRU recurrence ----------------
// grid (16, 2): one warp per PAIR of batch streams (same direction -> shared
// packed R in registers). Lane j owns h[j] of both streams; the two
// independent latency chains interleave. PG_=4 prefetch + split accumulator
// chains keep register use < 200 (R4 at PF=8 hit 245 regs and spilled).
// Backward direction (d=1) consumes MX in REVERSE time order (scan reverse=True).
__global__ __launch_bounds__(32) void gru_kernel(const float* __restrict__ grec, // [2][32][96]
                                                 const float* __restrict__ gb)   // [2][2][96]
{
    __shared__ __align__(16) float hs[2][2][32];   // [stream][parity][lane]

    int j  = threadIdx.x;
    int d  = blockIdx.y;
    int pr = blockIdx.x;
    int b0 = 2 * pr, b1 = 2 * pr + 1;

    const float* R = grec + d * 32 * 96;
    // Packed k-pair coefficients: Rz2[p] = (R[2p][j], R[2p+1][j]) etc. 96 regs total.
    unsigned long long Rz2[16], Rr2[16], Rh2[16];
#pragma unroll
    for (int p = 0; p < 16; p++) {
        Rz2[p] = pk2(R[(2 * p) * 96 + j],      R[(2 * p + 1) * 96 + j]);
        Rr2[p] = pk2(R[(2 * p) * 96 + 32 + j], R[(2 * p + 1) * 96 + 32 + j]);
        Rh2[p] = pk2(R[(2 * p) * 96 + 64 + j], R[(2 * p + 1) * 96 + 64 + j]);
    }
    const float* brc = gb + d * 192 + 96;     // b_rec
    float bz = brc[j], br = brc[32 + j], bh = brc[64 + j];

    const bool fwd = (d == 0);
    // base pointer at valid-data start (time 0 lives at array index PF_);
    // index: time*1024 + b*32 + j. Backward prefetch may reach time -PG_,
    // which lands in the left padding — in bounds, never consumed.
    const float4* mx = &g_MX[d][PF_][0][0];

    float4 buf0[PG_], buf1[PG_];
#pragma unroll
    for (int p = 0; p < PG_; p++) {
        int tt = fwd ? p : (S_ - 1 - p);
        buf0[p] = mx[tt * 1024 + b0 * 32 + j];
        buf1[p] = mx[tt * 1024 + b1 * 32 + j];
    }

    float h0 = 0.0f, h1 = 0.0f;

    for (int t0 = 0; t0 < S_; t0 += PG_) {
#pragma unroll
        for (int p = 0; p < PG_; p++) {
            int t  = t0 + p;                       // step counter
            int tt = fwd ? t : (S_ - 1 - t);       // time index consumed this step
            int par = t & 1;

            hs[0][par][j] = h0;                    // publish h to the warp
            hs[1][par][j] = h1;

            float4 m0 = buf0[p], m1 = buf1[p];
            int tp = fwd ? (t + PG_) : (S_ - 1 - t - PG_);
            buf0[p] = mx[tp * 1024 + b0 * 32 + j]; // prefetch PG_ steps ahead
            buf1[p] = mx[tp * 1024 + b1 * 32 + j];

            __syncwarp();

            // split accumulator chains (A: k 0..15, B: k 16..31) to halve dep latency
            unsigned long long az0 = pk2(m0.x + bz, 0.0f), az0B = pk2(0.f, 0.f);
            unsigned long long ar0 = pk2(m0.y + br, 0.0f), ar0B = pk2(0.f, 0.f);
            unsigned long long ah0 = pk2(bh, 0.0f),        ah0B = pk2(0.f, 0.f);
            unsigned long long az1 = pk2(m1.x + bz, 0.0f), az1B = pk2(0.f, 0.f);
            unsigned long long ar1 = pk2(m1.y + br, 0.0f), ar1B = pk2(0.f, 0.f);
            unsigned long long ah1 = pk2(bh, 0.0f),        ah1B = pk2(0.f, 0.f);

            const ulonglong2* hv0 = (const ulonglong2*)hs[0][par];
            const ulonglong2* hv1 = (const ulonglong2*)hs[1][par];
#pragma unroll
            for (int q = 0; q < 4; q++) {
                ulonglong2 v0 = hv0[q];            // k pairs 2q, 2q+1
                ulonglong2 v1 = hv1[q];
                ulonglong2 w0 = hv0[q + 4];        // k pairs 2q+8, 2q+9
                ulonglong2 w1 = hv1[q + 4];
                fma2(az0, v0.x, Rz2[2 * q]);
                fma2(ar0, v0.x, Rr2[2 * q]);
                fma2(ah0, v0.x, Rh2[2 * q]);
                fma2(az1, v1.x, Rz2[2 * q]);
                fma2(ar1, v1.x, Rr2[2 * q]);
                fma2(ah1, v1.x, Rh2[2 * q]);
                fma2(az0B, w0.x, Rz2[2 * q + 8]);
                fma2(ar0B, w0.x, Rr2[2 * q + 8]);
                fma2(ah0B, w0.x, Rh2[2 * q + 8]);
                fma2(az1B, w1.x, Rz2[2 * q + 8]);
                fma2(ar1B, w1.x, Rr2[2 * q + 8]);
                fma2(ah1B, w1.x, Rh2[2 * q + 8]);
                fma2(az0, v0.y, Rz2[2 * q + 1]);
                fma2(ar0, v0.y, Rr2[2 * q + 1]);
                fma2(ah0, v0.y, Rh2[2 * q + 1]);
                fma2(az1, v1.y, Rz2[2 * q + 1]);
                fma2(ar1, v1.y, Rr2[2 * q + 1]);
                fma2(ah1, v1.y, Rh2[2 * q + 1]);
                fma2(az0B, w0.y, Rz2[2 * q + 9]);
                fma2(ar0B, w0.y, Rr2[2 * q + 9]);
                fma2(ah0B, w0.y, Rh2[2 * q + 9]);
                fma2(az1B, w1.y, Rz2[2 * q + 9]);
                fma2(ar1B, w1.y, Rr2[2 * q + 9]);
                fma2(ah1B, w1.y, Rh2[2 * q + 9]);
            }

            float z0  = sigmoidf_(sum22(az0, az0B));
            float r0  = sigmoidf_(sum22(ar0, ar0B));
            float hh0 = tanhf_(fmaf(r0, sum22(ah0, ah0B), m0.z));
            h0 = fmaf(z0, h0 - hh0, hh0);

            float z1  = sigmoidf_(sum22(az1, az1B));
            float r1  = sigmoidf_(sum22(ar1, ar1B));
            float hh1 = tanhf_(fmaf(r1, sum22(ah1, ah1B), m1.z));
            h1 = fmaf(z1, h1 - hh1, hh1);

            g_CUR[(b0 * S_ + tt) * 64 + d * 32 + j] = h0;
            g_CUR[(b1 * S_ + tt) * 64 + d * 32 + j] = h1;
        }
    }
}

// ---------------- segment sum: SUMS[var[e]][f] += CUR[tok[e]][f] ----------------
__global__ void segsum_kernel(const int* __restrict__ tok, const int* __restrict__ var) {
    int g = blockIdx.x * 256 + threadIdx.x;
    if (g >= E_ * 64) return;
    int e = g >> 6, f = g & 63;
    int t = tok[e], v = var[e];
    atomicAdd(&g_SUMS[v * 64 + f], g_CUR[t * 64 + f]);
}

// ---------------- VE = SUMS / max(CNT,1) ----------------
__global__ void div_kernel(float* __restrict__ out, int to_out) {
    int i = blockIdx.x * 256 + threadIdx.x;
    if (i >= NV_ * 64) return;
    float c = g_CNT[i >> 6];
    float v = __fdividef(g_SUMS[i], fmaxf(c, 1.0f));
    if (to_out) out[i] = v;
    else        g_VE[i] = v;
}

// ---------------- X1 = CUR (copy), then scatter-add VE back ----------------
__global__ void copy_kernel() {
    int i = blockIdx.x * 256 + threadIdx.x;
    const float4* s = reinterpret_cast<const float4*>(g_CUR);
    float4* dst = reinterpret_cast<float4*>(g_X1);
    if (i < B_ * S_ * 16) dst[i] = s[i];
}

__global__ void scatter_kernel(const int* __restrict__ tok, const int* __restrict__ var) {
    int g = blockIdx.x * 256 + threadIdx.x;
    if (g >= E_ * 64) return;
    int e = g >> 6, f = g & 63;
    atomicAdd(&g_X1[tok[e] * 64 + f], g_VE[var[e] * 64 + f]);
}

// ---------------- classification = VE @ W (reads VE from d_out first half) --------
__global__ void linear_kernel(const float* __restrict__ ve, const float* __restrict__ W,
                              float* __restrict__ out) {
    __shared__ float Ws[64 * 64];
    for (int i = threadIdx.x; i < 64 * 64; i += 256) Ws[i] = W[i];
    __syncthreads();
    int g = blockIdx.x * 256 + threadIdx.x;
    if (g >= NV_ * 64) return;
    int v = g >> 6, c = g & 63;
    float acc = 0.0f;
#pragma unroll
    for (int f = 0; f < 64; f++)
        acc = fmaf(__ldg(&ve[v * 64 + f]), Ws[f * 64 + c], acc);
    out[g] = acc;
}

// ---------------- launcher ----------------
extern "C" void kernel_launch(void* const* d_in, const int* in_sizes, int n_in,
                              void* d_out, int out_size) {
    const float* emb  = (const float*)d_in[0];   // [10000,64]
    const float* gk   = (const float*)d_in[1];   // [2][2][64][96]
    const float* grec = (const float*)d_in[2];   // [2][2][32][96]
    const float* gb   = (const float*)d_in[3];   // [2][2][2][96]
    const float* W    = (const float*)d_in[4];   // [64,64]
    const int*   gidx = (const int*)d_in[5];     // [32,8192]
    const int*   slen = (const int*)d_in[6];     // [32]
    const int*   tok  = (const int*)d_in[7];     // [500000]
    const int*   var  = (const int*)d_in[8];     // [500000]
    float* out = (float*)d_out;                  // [NV*64] ve, then [NV*64] cls

    const int EG  = (E_ * 64) / 256;     // 125000
    const int VG  = (NV_ * 64) / 256;    // 12500
    const int CG  = (NV_ + 255) / 256;
    const int EB  = (E_ + 255) / 256;
    const int CPG = (B_ * S_ * 16) / 256;

    // counts (identical for every var_emb call)
    zero_cnt_kernel<<<CG, 256>>>();
    cnt_kernel<<<EB, 256>>>(var);

    // -------- layer 0 --------
    gemm_kernel<<<dim3(4096, 2), 256>>>(1, emb, gidx, slen, gk, gb);
    gru_kernel<<<dim3(16, 2), 32>>>(grec, gb);

    // consistency: variable means -> scatter back
    zero_sums_kernel<<<VG, 256>>>();
    segsum_kernel<<<EG, 256>>>(tok, var);
    div_kernel<<<VG, 256>>>(out, 0);         // -> g_VE
    copy_kernel<<<CPG, 256>>>();             // X1 = CUR
    scatter_kernel<<<EG, 256>>>(tok, var);   // X1 += scattered VE

    // -------- layer 1 --------
    gemm_kernel<<<dim3(4096, 2), 256>>>(0, emb, gidx, slen,
                                        gk + 2 * 64 * 96, gb + 384);
    gru_kernel<<<dim3(16, 2), 32>>>(grec + 2 * 32 * 96, gb + 384);

    // final variable embeddings + classification head
    zero_sums_kernel<<<VG, 256>>>();
    segsum_kernel<<<EG, 256>>>(tok, var);
    div_kernel<<<VG, 256>>>(out, 1);         // -> d_out[0 : NV*64]
    linear_kernel<<<VG, 256>>>(out, W, out + NV_ * 64);
}

// round 6
// speedup vs baseline: 1.3540x; 1.3334x over previous
#include <cuda_runtime.h>
#include <cuda_bf16.h>

// Problem constants (fixed by the dataset)
#define S_   8192
#define PF_  8      // MX padding + GRU prefetch depth
#define B_   32
#define E_   500000
#define NV_  50000

// ---------------- static device scratch (no allocs allowed) ----------------
// MX padded PF_ on BOTH sides: valid data at time index t+PF_.
__device__ float4 g_MX[2][S_ + 2 * PF_][B_][32];  // x@K+b_in per dir: (z,r,h,pad)
__device__ float  g_CUR[B_ * S_ * 64];    // GRU layer output, concat(f,b)
__device__ float  g_X1[B_ * S_ * 64];     // consistency-adjusted input to layer 1
__device__ float  g_SUMS[NV_ * 64];
__device__ float  g_VE[NV_ * 64];
__device__ float  g_CNT[NV_];

__device__ __forceinline__ float sigmoidf_(float x) {
    return __fdividef(1.0f, 1.0f + __expf(-x));
}
__device__ __forceinline__ float tanhf_(float x) {
    // tanh(x) = 1 - 2/(e^{2x}+1); saturates correctly at +/-1 for large |x|
    return 1.0f - __fdividef(2.0f, __expf(2.0f * x) + 1.0f);
}
// Fast sigmoid for the r gate (critical path): sigmoid(x) = 0.5*tanh(x/2) + 0.5.
// tanh.approx.f32 is a single SFU op (~16 cyc) vs EX2+ADD+RCP (~44 cyc).
__device__ __forceinline__ float sigmoid_fast_(float x) {
    float t;
    asm("tanh.approx.f32 %0, %1;" : "=f"(t) : "f"(x * 0.5f));
    return fmaf(t, 0.5f, 0.5f);
}

// ---- packed fp32x2 helpers (Blackwell FFMA2/FADD2: PTX f32x2 ops) ----
__device__ __forceinline__ unsigned long long pk2(float lo, float hi) {
    unsigned long long r;
    asm("mov.b64 %0, {%1, %2};" : "=l"(r) : "f"(lo), "f"(hi));
    return r;
}
__device__ __forceinline__ void fma2(unsigned long long& d,
                                     unsigned long long a, unsigned long long b) {
    asm("fma.rn.f32x2 %0, %1, %2, %0;" : "+l"(d) : "l"(a), "l"(b));
}
__device__ __forceinline__ unsigned long long add2(unsigned long long a,
                                                   unsigned long long b) {
    unsigned long long r;
    asm("add.rn.f32x2 %0, %1, %2;" : "=l"(r) : "l"(a), "l"(b));
    return r;
}
__device__ __forceinline__ float sum2(unsigned long long v) {
    float a, b;
    asm("mov.b64 {%0, %1}, %2;" : "=f"(a), "=f"(b) : "l"(v));
    return a + b;
}
// Reduce four packed-pair accumulators to a scalar (tree: depth 3 ADD2 + FADD)
__device__ __forceinline__ float rsum4(unsigned long long a, unsigned long long b,
                                       unsigned long long c, unsigned long long d) {
    return sum2(add2(add2(a, b), add2(c, d)));
}

// ---------------- zero kernels ----------------
__global__ void zero_sums_kernel() {
    int i = blockIdx.x * 256 + threadIdx.x;
    if (i < NV_ * 64) g_SUMS[i] = 0.0f;
}
__global__ void zero_cnt_kernel() {
    int i = blockIdx.x * 256 + threadIdx.x;
    if (i < NV_) g_CNT[i] = 0.0f;
}

// ---------------- per-variable occurrence counts ----------------
__global__ void cnt_kernel(const int* __restrict__ var) {
    int e = blockIdx.x * 256 + threadIdx.x;
    if (e < E_) atomicAdd(&g_CNT[var[e]], 1.0f);
}

// ---------------- input GEMM: MX[d][t+PF][b][j] = (x*mask)@K + b_in ----------------
// grid (4096, 2), block 256. Tile = 64 consecutive tokens of one batch row.
__global__ void gemm_kernel(int use_emb,
                            const float* __restrict__ emb,
                            const int*   __restrict__ gidx,
                            const int*   __restrict__ slen,
                            const float* __restrict__ gk,   // [2][64][96] (this layer)
                            const float* __restrict__ gb)   // [2][2][96]  (this layer)
{
    __shared__ float Xs[64][64];
    __shared__ float Ks[64 * 96];

    int d    = blockIdx.y;
    int tile = blockIdx.x;
    int b    = tile >> 7;            // 128 tiles per batch row (8192/64)
    int t0   = (tile & 127) << 6;
    int tid  = threadIdx.x;
    int len  = slen[b];

    for (int i = tid; i < 64 * 64; i += 256) {
        int tt = i >> 6, k = i & 63;
        int t = t0 + tt;
        float v = 0.0f;
        if (t < len) {
            if (use_emb) {
                int id = gidx[b * S_ + t];
                v = emb[id * 64 + k];
            } else {
                v = g_X1[(b * S_ + t) * 64 + k];
            }
        }
        Xs[tt][k] = v;
    }
    const float* Kd = gk + d * 64 * 96;
    for (int i = tid; i < 64 * 96; i += 256) Ks[i] = Kd[i];
    __syncthreads();

    int j = tid & 31, tg = tid >> 5;
    float a0[8], a1[8], a2[8];
#pragma unroll
    for (int i = 0; i < 8; i++) { a0[i] = 0.f; a1[i] = 0.f; a2[i] = 0.f; }

#pragma unroll 4
    for (int k = 0; k < 64; k++) {
        float kz = Ks[k * 96 + j];
        float kr = Ks[k * 96 + 32 + j];
        float kh = Ks[k * 96 + 64 + j];
#pragma unroll
        for (int i = 0; i < 8; i++) {
            float x = Xs[tg * 8 + i][k];
            a0[i] = fmaf(x, kz, a0[i]);
            a1[i] = fmaf(x, kr, a1[i]);
            a2[i] = fmaf(x, kh, a2[i]);
        }
    }

    const float* bin = gb + d * 192;          // b_in for this dir
    float bz = bin[j], br = bin[32 + j], bh = bin[64 + j];
#pragma unroll
    for (int i = 0; i < 8; i++) {
        int t = t0 + tg * 8 + i;
        g_MX[d][t + PF_][b][j] = make_float4(a0[i] + bz, a1[i] + br, a2[i] + bh, 0.0f);
    }
}

// ---------------- GRU recurrence ----------------
// grid (32, 2): one warp per (batch, direction) stream. Lane j owns h[j].
// h broadcast via double-buffered smem; dot products via packed fma.rn.f32x2
// in FOUR split chains per gate (dep depth 16 -> 4) combined by an add2 tree.
// r gate uses tanh.approx-based sigmoid (on the critical path); z and the
// candidate tanh remain precise.
// Backward direction (d=1) consumes MX in REVERSE time order (scan reverse=True).
__global__ __launch_bounds__(32) void gru_kernel(const float* __restrict__ grec, // [2][32][96]
                                                 const float* __restrict__ gb)   // [2][2][96]
{
    __shared__ __align__(16) float hs[2][32];

    int j = threadIdx.x;
    int d = blockIdx.y;
    int b = blockIdx.x;

    const float* R = grec + d * 32 * 96;
    // Packed k-pair coefficients: Rz2[p] = (R[2p][j], R[2p+1][j]) etc. 96 regs total.
    unsigned long long Rz2[16], Rr2[16], Rh2[16];
#pragma unroll
    for (int p = 0; p < 16; p++) {
        Rz2[p] = pk2(R[(2 * p) * 96 + j],      R[(2 * p + 1) * 96 + j]);
        Rr2[p] = pk2(R[(2 * p) * 96 + 32 + j], R[(2 * p + 1) * 96 + 32 + j]);
        Rh2[p] = pk2(R[(2 * p) * 96 + 64 + j], R[(2 * p + 1) * 96 + 64 + j]);
    }
    const float* brc = gb + d * 192 + 96;     // b_rec
    float bz = brc[j], br = brc[32 + j], bh = brc[64 + j];

    const bool fwd = (d == 0);
    // base pointer at valid-data start (time 0 lives at array index PF_);
    // index: time*1024 + b*32 + j. Backward prefetch may reach time -PF_,
    // which lands in the left padding — in bounds, never consumed.
    const float4* mx = &g_MX[d][PF_][0][0];

    float4 buf[PF_];
#pragma unroll
    for (int p = 0; p < PF_; p++) {
        int tt = fwd ? p : (S_ - 1 - p);
        buf[p] = mx[tt * 1024 + b * 32 + j];
    }

    float h = 0.0f;

    for (int t0 = 0; t0 < S_; t0 += PF_) {
#pragma unroll
        for (int p = 0; p < PF_; p++) {
            int t  = t0 + p;                       // step counter
            int tt = fwd ? t : (S_ - 1 - t);       // time index consumed this step
            int par = t & 1;

            hs[par][j] = h;                        // publish h to the warp

            float4 m = buf[p];
            int tp = fwd ? (t + PF_) : (S_ - 1 - t - PF_);
            buf[p] = mx[tp * 1024 + b * 32 + j];   // prefetch PF_ steps ahead

            __syncwarp();

            // 4 split chains per gate: chain c accumulates k-pairs {c, c+4, ...}
            unsigned long long az0 = pk2(m.x + bz, 0.0f), az1 = 0ULL, az2 = 0ULL, az3 = 0ULL;
            unsigned long long ar0 = pk2(m.y + br, 0.0f), ar1 = 0ULL, ar2 = 0ULL, ar3 = 0ULL;
            unsigned long long ah0 = pk2(bh, 0.0f),       ah1 = 0ULL, ah2 = 0ULL, ah3 = 0ULL;

            const ulonglong2* hv = (const ulonglong2*)hs[par];
#pragma unroll
            for (int q = 0; q < 4; q++) {
                ulonglong2 v = hv[q];              // k pairs 2q, 2q+1
                ulonglong2 w = hv[q + 4];          // k pairs 2q+8, 2q+9
                fma2(ar0, v.x, Rr2[2 * q]);
                fma2(ar1, v.y, Rr2[2 * q + 1]);
                fma2(ar2, w.x, Rr2[2 * q + 8]);
                fma2(ar3, w.y, Rr2[2 * q + 9]);
                fma2(ah0, v.x, Rh2[2 * q]);
                fma2(ah1, v.y, Rh2[2 * q + 1]);
                fma2(ah2, w.x, Rh2[2 * q + 8]);
                fma2(ah3, w.y, Rh2[2 * q + 9]);
                fma2(az0, v.x, Rz2[2 * q]);
                fma2(az1, v.y, Rz2[2 * q + 1]);
                fma2(az2, w.x, Rz2[2 * q + 8]);
                fma2(az3, w.y, Rz2[2 * q + 9]);
            }

            // critical path: ar tree -> fast sigmoid -> fma -> precise tanh -> update
            float r  = sigmoid_fast_(rsum4(ar0, ar1, ar2, ar3));
            float hh = tanhf_(fmaf(r, rsum4(ah0, ah1, ah2, ah3), m.z));
            float z  = sigmoidf_(rsum4(az0, az1, az2, az3));   // off-path, precise
            h = fmaf(z, h - hh, hh);

            g_CUR[(b * S_ + tt) * 64 + d * 32 + j] = h;
        }
    }
}

// ---------------- segment sum: SUMS[var[e]][f] += CUR[tok[e]][f] ----------------
__global__ void segsum_kernel(const int* __restrict__ tok, const int* __restrict__ var) {
    int g = blockIdx.x * 256 + threadIdx.x;
    if (g >= E_ * 64) return;
    int e = g >> 6, f = g & 63;
    int t = tok[e], v = var[e];
    atomicAdd(&g_SUMS[v * 64 + f], g_CUR[t * 64 + f]);
}

// ---------------- VE = SUMS / max(CNT,1) ----------------
__global__ void div_kernel(float* __restrict__ out, int to_out) {
    int i = blockIdx.x * 256 + threadIdx.x;
    if (i >= NV_ * 64) return;
    float c = g_CNT[i >> 6];
    float v = __fdividef(g_SUMS[i], fmaxf(c, 1.0f));
    if (to_out) out[i] = v;
    else        g_VE[i] = v;
}

// ---------------- X1 = CUR (copy), then scatter-add VE back ----------------
__global__ void copy_kernel() {
    int i = blockIdx.x * 256 + threadIdx.x;
    const float4* s = reinterpret_cast<const float4*>(g_CUR);
    float4* dst = reinterpret_cast<float4*>(g_X1);
    if (i < B_ * S_ * 16) dst[i] = s[i];
}

__global__ void scatter_kernel(const int* __restrict__ tok, const int* __restrict__ var) {
    int g = blockIdx.x * 256 + threadIdx.x;
    if (g >= E_ * 64) return;
    int e = g >> 6, f = g & 63;
    atomicAdd(&g_X1[tok[e] * 64 + f], g_VE[var[e] * 64 + f]);
}

// ---------------- classification = VE @ W (reads VE from d_out first half) --------
__global__ void linear_kernel(const float* __restrict__ ve, const float* __restrict__ W,
                              float* __restrict__ out) {
    __shared__ float Ws[64 * 64];
    for (int i = threadIdx.x; i < 64 * 64; i += 256) Ws[i] = W[i];
    __syncthreads();
    int g = blockIdx.x * 256 + threadIdx.x;
    if (g >= NV_ * 64) return;
    int v = g >> 6, c = g & 63;
    float acc = 0.0f;
#pragma unroll
    for (int f = 0; f < 64; f++)
        acc = fmaf(__ldg(&ve[v * 64 + f]), Ws[f * 64 + c], acc);
    out[g] = acc;
}

// ---------------- launcher ----------------
extern "C" void kernel_launch(void* const* d_in, const int* in_sizes, int n_in,
                              void* d_out, int out_size) {
    const float* emb  = (const float*)d_in[0];   // [10000,64]
    const float* gk   = (const float*)d_in[1];   // [2][2][64][96]
    const float* grec = (const float*)d_in[2];   // [2][2][32][96]
    const float* gb   = (const float*)d_in[3];   // [2][2][2][96]
    const float* W    = (const float*)d_in[4];   // [64,64]
    const int*   gidx = (const int*)d_in[5];     // [32,8192]
    const int*   slen = (const int*)d_in[6];     // [32]
    const int*   tok  = (const int*)d_in[7];     // [500000]
    const int*   var  = (const int*)d_in[8];     // [500000]
    float* out = (float*)d_out;                  // [NV*64] ve, then [NV*64] cls

    const int EG  = (E_ * 64) / 256;     // 125000
    const int VG  = (NV_ * 64) / 256;    // 12500
    const int CG  = (NV_ + 255) / 256;
    const int EB  = (E_ + 255) / 256;
    const int CPG = (B_ * S_ * 16) / 256;

    // counts (identical for every var_emb call)
    zero_cnt_kernel<<<CG, 256>>>();
    cnt_kernel<<<EB, 256>>>(var);

    // -------- layer 0 --------
    gemm_kernel<<<dim3(4096, 2), 256>>>(1, emb, gidx, slen, gk, gb);
    gru_kernel<<<dim3(B_, 2), 32>>>(grec, gb);

    // consistency: variable means -> scatter back
    zero_sums_kernel<<<VG, 256>>>();
    segsum_kernel<<<EG, 256>>>(tok, var);
    div_kernel<<<VG, 256>>>(out, 0);         // -> g_VE
    copy_kernel<<<CPG, 256>>>();             // X1 = CUR
    scatter_kernel<<<EG, 256>>>(tok, var);   // X1 += scattered VE

    // -------- layer 1 --------
    gemm_kernel<<<dim3(4096, 2), 256>>>(0, emb, gidx, slen,
                                        gk + 2 * 64 * 96, gb + 384);
    gru_kernel<<<dim3(B_, 2), 32>>>(grec + 2 * 32 * 96, gb + 384);

    // final variable embeddings + classification head
    zero_sums_kernel<<<VG, 256>>>();
    segsum_kernel<<<EG, 256>>>(tok, var);
    div_kernel<<<VG, 256>>>(out, 1);         // -> d_out[0 : NV*64]
    linear_kernel<<<VG, 256>>>(out, W, out + NV_ * 64);
}

// round 7
// speedup vs baseline: 2.2296x; 1.6466x over previous
#include <cuda_runtime.h>
#include <cuda_bf16.h>

// Problem constants (fixed by the dataset)
#define S_   8192
#define PF_  8
#define B_   32
#define E_   500000
#define NV_  50000

// ---------------- static device scratch (no allocs allowed) ----------------
// MX padded PF_ on BOTH sides: valid data at time index t+PF_.
__device__ float4 g_MX[2][S_ + 2 * PF_][B_][32];  // x@K+b_in per dir: (z,r,h,pad)
__device__ float  g_CUR[B_ * S_ * 64];    // GRU layer output, concat(f,b)
__device__ float  g_X1[B_ * S_ * 64];     // consistency-adjusted input to layer 1
__device__ float  g_SUMS[NV_ * 64];
__device__ float  g_VE[NV_ * 64];
__device__ float  g_CNT[NV_];

__device__ __forceinline__ float sigmoidf_(float x) {
    return __fdividef(1.0f, 1.0f + __expf(-x));
}
__device__ __forceinline__ float tanhf_(float x) {
    // tanh(x) = 1 - 2/(e^{2x}+1); saturates correctly at +/-1 for large |x|
    return 1.0f - __fdividef(2.0f, __expf(2.0f * x) + 1.0f);
}

// ---- packed fp32x2 helpers (Blackwell FFMA2: PTX fma.rn.f32x2 only) ----
__device__ __forceinline__ unsigned long long pk2(float lo, float hi) {
    unsigned long long r;
    asm("mov.b64 %0, {%1, %2};" : "=l"(r) : "f"(lo), "f"(hi));
    return r;
}
__device__ __forceinline__ void fma2(unsigned long long& d,
                                     unsigned long long a, unsigned long long b) {
    asm("fma.rn.f32x2 %0, %1, %2, %0;" : "+l"(d) : "l"(a), "l"(b));
}
__device__ __forceinline__ float sum2(unsigned long long v) {
    float a, b;
    asm("mov.b64 {%0, %1}, %2;" : "=f"(a), "=f"(b) : "l"(v));
    return a + b;
}

// ---- vectorized global reduction: 4 floats per RED (PTX 8.1+, sm_90+) ----
__device__ __forceinline__ void red_add_v4(float* ptr, float4 v) {
    asm volatile("red.global.add.v4.f32 [%0], {%1, %2, %3, %4};"
                 :: "l"(ptr), "f"(v.x), "f"(v.y), "f"(v.z), "f"(v.w)
                 : "memory");
}

// ---------------- zero kernels ----------------
__global__ void zero_sums_kernel() {
    int i = blockIdx.x * 256 + threadIdx.x;
    if (i < NV_ * 64) g_SUMS[i] = 0.0f;
}
__global__ void zero_cnt_kernel() {
    int i = blockIdx.x * 256 + threadIdx.x;
    if (i < NV_) g_CNT[i] = 0.0f;
}

// ---------------- per-variable occurrence counts ----------------
__global__ void cnt_kernel(const int* __restrict__ var) {
    int e = blockIdx.x * 256 + threadIdx.x;
    if (e < E_) atomicAdd(&g_CNT[var[e]], 1.0f);
}

// ---------------- input GEMM: MX[d][t+PF][b][j] = (x*mask)@K + b_in ----------------
// grid (4096, 2), block 256. Tile = 64 consecutive tokens of one batch row.
__global__ void gemm_kernel(int use_emb,
                            const float* __restrict__ emb,
                            const int*   __restrict__ gidx,
                            const int*   __restrict__ slen,
                            const float* __restrict__ gk,   // [2][64][96] (this layer)
                            const float* __restrict__ gb)   // [2][2][96]  (this layer)
{
    __shared__ float Xs[64][64];
    __shared__ float Ks[64 * 96];

    int d    = blockIdx.y;
    int tile = blockIdx.x;
    int b    = tile >> 7;            // 128 tiles per batch row (8192/64)
    int t0   = (tile & 127) << 6;
    int tid  = threadIdx.x;
    int len  = slen[b];

    for (int i = tid; i < 64 * 64; i += 256) {
        int tt = i >> 6, k = i & 63;
        int t = t0 + tt;
        float v = 0.0f;
        if (t < len) {
            if (use_emb) {
                int id = gidx[b * S_ + t];
                v = emb[id * 64 + k];
            } else {
                v = g_X1[(b * S_ + t) * 64 + k];
            }
        }
        Xs[tt][k] = v;
    }
    const float* Kd = gk + d * 64 * 96;
    for (int i = tid; i < 64 * 96; i += 256) Ks[i] = Kd[i];
    __syncthreads();

    int j = tid & 31, tg = tid >> 5;
    float a0[8], a1[8], a2[8];
#pragma unroll
    for (int i = 0; i < 8; i++) { a0[i] = 0.f; a1[i] = 0.f; a2[i] = 0.f; }

#pragma unroll 4
    for (int k = 0; k < 64; k++) {
        float kz = Ks[k * 96 + j];
        float kr = Ks[k * 96 + 32 + j];
        float kh = Ks[k * 96 + 64 + j];
#pragma unroll
        for (int i = 0; i < 8; i++) {
            float x = Xs[tg * 8 + i][k];
            a0[i] = fmaf(x, kz, a0[i]);
            a1[i] = fmaf(x, kr, a1[i]);
            a2[i] = fmaf(x, kh, a2[i]);
        }
    }

    const float* bin = gb + d * 192;          // b_in for this dir
    float bz = bin[j], br = bin[32 + j], bh = bin[64 + j];
#pragma unroll
    for (int i = 0; i < 8; i++) {
        int t = t0 + tg * 8 + i;
        g_MX[d][t + PF_][b][j] = make_float4(a0[i] + bz, a1[i] + br, a2[i] + bh, 0.0f);
    }
}

// ---------------- GRU recurrence (exact R3 version — best measured) ----------------
// grid (32, 2): one warp per (batch, direction) stream. Lane j owns h[j].
// h broadcast via double-buffered smem (1 STS + syncwarp + 8 broadcast LDS.128),
// dot products via packed fma.rn.f32x2 over k-pairs (48 FFMA2 instead of 96 FFMA).
// Backward direction (d=1) consumes MX in REVERSE time order (scan reverse=True).
__global__ __launch_bounds__(32) void gru_kernel(const float* __restrict__ grec, // [2][32][96]
                                                 const float* __restrict__ gb)   // [2][2][96]
{
    __shared__ __align__(16) float hs[2][32];

    int j = threadIdx.x;
    int d = blockIdx.y;
    int b = blockIdx.x;

    const float* R = grec + d * 32 * 96;
    // Packed k-pair coefficients: Rz2[p] = (R[2p][j], R[2p+1][j]) etc. 96 regs total.
    unsigned long long Rz2[16], Rr2[16], Rh2[16];
#pragma unroll
    for (int p = 0; p < 16; p++) {
        Rz2[p] = pk2(R[(2 * p) * 96 + j],      R[(2 * p + 1) * 96 + j]);
        Rr2[p] = pk2(R[(2 * p) * 96 + 32 + j], R[(2 * p + 1) * 96 + 32 + j]);
        Rh2[p] = pk2(R[(2 * p) * 96 + 64 + j], R[(2 * p + 1) * 96 + 64 + j]);
    }
    const float* brc = gb + d * 192 + 96;     // b_rec
    float bz = brc[j], br = brc[32 + j], bh = brc[64 + j];

    const bool fwd = (d == 0);
    // base pointer at valid-data start (time 0 lives at array index PF_);
    // index: time*1024 + b*32 + j. Backward prefetch may reach time -PF_,
    // which lands in the left padding — in bounds, never consumed.
    const float4* mx = &g_MX[d][PF_][0][0];

    float4 buf[PF_];
#pragma unroll
    for (int p = 0; p < PF_; p++) {
        int tt = fwd ? p : (S_ - 1 - p);
        buf[p] = mx[tt * 1024 + b * 32 + j];
    }

    float h = 0.0f;

    for (int t0 = 0; t0 < S_; t0 += PF_) {
#pragma unroll
        for (int p = 0; p < PF_; p++) {
            int t  = t0 + p;                       // step counter
            int tt = fwd ? t : (S_ - 1 - t);       // time index consumed this step
            int par = t & 1;

            hs[par][j] = h;                        // publish h to the warp

            float4 m = buf[p];
            int tp = fwd ? (t + PF_) : (S_ - 1 - t - PF_);
            buf[p] = mx[tp * 1024 + b * 32 + j];   // prefetch PF_ steps ahead

            __syncwarp();

            // accumulators: z/r fold in m + b_rec; h-gate holds only (h@Rh + b_rec_h)
            unsigned long long az = pk2(m.x + bz, 0.0f);
            unsigned long long ar = pk2(m.y + br, 0.0f);
            unsigned long long ah = pk2(bh, 0.0f);

            const ulonglong2* hv = (const ulonglong2*)hs[par];
#pragma unroll
            for (int q = 0; q < 8; q++) {
                ulonglong2 v = hv[q];              // (h[4q],h[4q+1]) , (h[4q+2],h[4q+3])
                fma2(az, v.x, Rz2[2 * q]);
                fma2(ar, v.x, Rr2[2 * q]);
                fma2(ah, v.x, Rh2[2 * q]);
                fma2(az, v.y, Rz2[2 * q + 1]);
                fma2(ar, v.y, Rr2[2 * q + 1]);
                fma2(ah, v.y, Rh2[2 * q + 1]);
            }

            float z  = sigmoidf_(sum2(az));
            float r  = sigmoidf_(sum2(ar));
            float hh = tanhf_(fmaf(r, sum2(ah), m.z));
            h = fmaf(z, h - hh, hh);

            g_CUR[(b * S_ + tt) * 64 + d * 32 + j] = h;
        }
    }
}

// ---------------- segment sum: SUMS[var[e]][·] += CUR[tok[e]][·]  (RED.v4) --------
// 16 threads per edge; thread q handles features [4q, 4q+4).
__global__ void segsum_kernel(const int* __restrict__ tok, const int* __restrict__ var) {
    int g = blockIdx.x * 256 + threadIdx.x;
    if (g >= E_ * 16) return;
    int e = g >> 4, q = g & 15;
    int t = tok[e], v = var[e];
    float4 val = *(const float4*)&g_CUR[t * 64 + q * 4];
    red_add_v4(&g_SUMS[v * 64 + q * 4], val);
}

// ---------------- VE = SUMS / max(CNT,1) ----------------
__global__ void div_kernel(float* __restrict__ out, int to_out) {
    int i = blockIdx.x * 256 + threadIdx.x;
    if (i >= NV_ * 64) return;
    float c = g_CNT[i >> 6];
    float v = __fdividef(g_SUMS[i], fmaxf(c, 1.0f));
    if (to_out) out[i] = v;
    else        g_VE[i] = v;
}

// ---------------- X1 = CUR (copy), then scatter-add VE back ----------------
__global__ void copy_kernel() {
    int i = blockIdx.x * 256 + threadIdx.x;
    const float4* s = reinterpret_cast<const float4*>(g_CUR);
    float4* dst = reinterpret_cast<float4*>(g_X1);
    if (i < B_ * S_ * 16) dst[i] = s[i];
}

// scatter: X1[tok[e]][·] += VE[var[e]][·]  (RED.v4, 16 threads per edge)
__global__ void scatter_kernel(const int* __restrict__ tok, const int* __restrict__ var) {
    int g = blockIdx.x * 256 + threadIdx.x;
    if (g >= E_ * 16) return;
    int e = g >> 4, q = g & 15;
    int t = tok[e], v = var[e];
    float4 val = *(const float4*)&g_VE[v * 64 + q * 4];
    red_add_v4(&g_X1[t * 64 + q * 4], val);
}

// ---------------- classification = VE @ W (reads VE from d_out first half) --------
__global__ void linear_kernel(const float* __restrict__ ve, const float* __restrict__ W,
                              float* __restrict__ out) {
    __shared__ float Ws[64 * 64];
    for (int i = threadIdx.x; i < 64 * 64; i += 256) Ws[i] = W[i];
    __syncthreads();
    int g = blockIdx.x * 256 + threadIdx.x;
    if (g >= NV_ * 64) return;
    int v = g >> 6, c = g & 63;
    float acc = 0.0f;
#pragma unroll
    for (int f = 0; f < 64; f++)
        acc = fmaf(__ldg(&ve[v * 64 + f]), Ws[f * 64 + c], acc);
    out[g] = acc;
}

// ---------------- launcher ----------------
extern "C" void kernel_launch(void* const* d_in, const int* in_sizes, int n_in,
                              void* d_out, int out_size) {
    const float* emb  = (const float*)d_in[0];   // [10000,64]
    const float* gk   = (const float*)d_in[1];   // [2][2][64][96]
    const float* grec = (const float*)d_in[2];   // [2][2][32][96]
    const float* gb   = (const float*)d_in[3];   // [2][2][2][96]
    const float* W    = (const float*)d_in[4];   // [64,64]
    const int*   gidx = (const int*)d_in[5];     // [32,8192]
    const int*   slen = (const int*)d_in[6];     // [32]
    const int*   tok  = (const int*)d_in[7];     // [500000]
    const int*   var  = (const int*)d_in[8];     // [500000]
    float* out = (float*)d_out;                  // [NV*64] ve, then [NV*64] cls

    const int EG16 = (E_ * 16) / 256;    // 31250  (v4-RED passes)
    const int VG   = (NV_ * 64) / 256;   // 12500
    const int CG   = (NV_ + 255) / 256;
    const int EB   = (E_ + 255) / 256;
    const int CPG  = (B_ * S_ * 16) / 256;

    // counts (identical for every var_emb call)
    zero_cnt_kernel<<<CG, 256>>>();
    cnt_kernel<<<EB, 256>>>(var);

    // -------- layer 0 --------
    gemm_kernel<<<dim3(4096, 2), 256>>>(1, emb, gidx, slen, gk, gb);
    gru_kernel<<<dim3(B_, 2), 32>>>(grec, gb);

    // consistency: variable means -> scatter back
    zero_sums_kernel<<<VG, 256>>>();
    segsum_kernel<<<EG16, 256>>>(tok, var);
    div_kernel<<<VG, 256>>>(out, 0);         // -> g_VE
    copy_kernel<<<CPG, 256>>>();             // X1 = CUR
    scatter_kernel<<<EG16, 256>>>(tok, var); // X1 += scattered VE

    // -------- layer 1 --------
    gemm_kernel<<<dim3(4096, 2), 256>>>(0, emb, gidx, slen,
                                        gk + 2 * 64 * 96, gb + 384);
    gru_kernel<<<dim3(B_, 2), 32>>>(grec + 2 * 32 * 96, gb + 384);

    // final variable embeddings + classification head
    zero_sums_kernel<<<VG, 256>>>();
    segsum_kernel<<<EG16, 256>>>(tok, var);
    div_kernel<<<VG, 256>>>(out, 1);         // -> d_out[0 : NV*64]
    linear_kernel<<<VG, 256>>>(out, W, out + NV_ * 64);
}